// round 3
// baseline (speedup 1.0000x reference)
#include <cuda_runtime.h>
#include <cuda_bf16.h>
#include <math.h>
#include <stdint.h>

// Problem constants
#define TT  512
#define BB  32
#define HH  256      // per-direction hidden
#define EMB_ 256
#define HID_ 512
#define KK  24
#define START_TAG 22
#define STOP_TAG 23
#define NEGV (-10000.0f)

// ---------------------------------------------------------------------------
// Device scratch (allocation-free rule: __device__ globals)
// ---------------------------------------------------------------------------
__device__ float g_ig[2][TT][1024][BB];      // input-gate preactivations, [dir][t][gatecol][b]  (128 MB)
__device__ float g_hall[TT][HID_][BB];       // concat hidden states, [t][hid][b], hid = dir*256+col (32 MB)
__device__ float g_h[2][2][HH][BB];          // h double buffer: [phase][dir][col][b]
__device__ float g_feats[TT][BB][KK];        // CRF emission feats
__device__ unsigned g_bar_count[2];
__device__ volatile unsigned g_bar_gen[2];

// ---------------------------------------------------------------------------
// Per-direction software grid barrier (64 blocks per direction, all resident)
// ---------------------------------------------------------------------------
__device__ __forceinline__ void dir_barrier(int dir) {
    __syncthreads();
    if (threadIdx.x == 0) {
        __threadfence();
        unsigned gen = g_bar_gen[dir];
        if (atomicAdd(&g_bar_count[dir], 1u) == 63u) {
            g_bar_count[dir] = 0u;
            __threadfence();
            g_bar_gen[dir] = gen + 1u;
        } else {
            while (g_bar_gen[dir] == gen) { }
            __threadfence();
        }
    }
    __syncthreads();
}

// ---------------------------------------------------------------------------
// Kernel 1: ig[d][t][col][b] = emb[sent[b][t]] @ W_ih^T + b_ih + b_hh
// grid = 1024 (d*512 + t), block = 256.  smem: x_s[256][34], w_s[64][256]
// ---------------------------------------------------------------------------
__global__ void __launch_bounds__(256) ig_kernel(
    const int* __restrict__ sentence, const float* __restrict__ emb,
    const float* __restrict__ w_ih_f, const float* __restrict__ b_ih_f, const float* __restrict__ b_hh_f,
    const float* __restrict__ w_ih_b, const float* __restrict__ b_ih_b, const float* __restrict__ b_hh_b)
{
    extern __shared__ float sm[];
    float* x_s = sm;                  // [e][b] stride 34 (pad: conflict-free, float2-aligned)
    float* w_s = sm + 256 * 34;       // [c][e] 64x256 chunk

    int d = blockIdx.x >> 9;
    int t = blockIdx.x & 511;
    const float* w_ih = d ? w_ih_b : w_ih_f;
    const float* bi   = d ? b_ih_b : b_ih_f;
    const float* bh   = d ? b_hh_b : b_hh_f;
    int tid = threadIdx.x;

    // gather embedding rows: x_s[e][b], e = tid (coalesced over e per row)
    for (int b = 0; b < BB; ++b) {
        int tok = __ldg(&sentence[b * TT + t]);
        x_s[tid * 34 + b] = __ldg(&emb[tok * EMB_ + tid]);
    }

    int bh2 = tid & 15;               // batch pair index
    int b2  = bh2 * 2;
    int cg  = tid >> 4;               // 16 col-groups of 4 cols

    for (int chunk = 0; chunk < 16; ++chunk) {
        int colBase = chunk * 64;
        __syncthreads();              // prior reads of w_s / x_s writes done
        for (int i = tid; i < 64 * 256; i += 256)
            w_s[i] = w_ih[colBase * 256 + i];          // coalesced
        __syncthreads();

        float a0=0.f,a1=0.f,a2=0.f,a3=0.f,a4=0.f,a5=0.f,a6=0.f,a7=0.f;
        #pragma unroll 4
        for (int e = 0; e < 256; ++e) {
            float2 xv = *(const float2*)&x_s[e * 34 + b2];
            float w0 = w_s[(cg*4+0)*256 + e];
            float w1 = w_s[(cg*4+1)*256 + e];
            float w2 = w_s[(cg*4+2)*256 + e];
            float w3 = w_s[(cg*4+3)*256 + e];
            a0 += xv.x*w0; a1 += xv.y*w0;
            a2 += xv.x*w1; a3 += xv.y*w1;
            a4 += xv.x*w2; a5 += xv.y*w2;
            a6 += xv.x*w3; a7 += xv.y*w3;
        }
        float r[8] = {a0,a1,a2,a3,a4,a5,a6,a7};
        #pragma unroll
        for (int j = 0; j < 4; ++j) {
            int col = colBase + cg * 4 + j;
            float bias = __ldg(&bi[col]) + __ldg(&bh[col]);
            g_ig[d][t][col][b2]   = r[2*j]   + bias;
            g_ig[d][t][col][b2+1] = r[2*j+1] + bias;
        }
    }
}

// ---------------------------------------------------------------------------
// Kernel 2: persistent bidirectional LSTM recurrence.
// grid = 128 (dir = bx>>6, 64 blocks/dir, each owns 4 h-cols = 16 gate cols)
// block = 256.  smem: w_s[16][256], h_s[256][32], g_s[16][32]
// ---------------------------------------------------------------------------
__global__ void __launch_bounds__(256) lstm_rec(
    const float* __restrict__ w_hh_f, const float* __restrict__ w_hh_b,
    const float* __restrict__ h0, const float* __restrict__ c0)
{
    extern __shared__ float sm[];
    float* w_s = sm;                  // [l][k]  l = gate*4 + sub
    float* h_s = sm + 16 * 256;       // [k][b]
    float* g_s = sm + 16 * 256 + 256 * 32;  // [l][b]

    int bx  = blockIdx.x;
    int dir = bx >> 6;
    int blk = bx & 63;
    int j0  = blk * 4;                // first owned h-col
    const float* w_hh = dir ? w_hh_b : w_hh_f;
    int tid = threadIdx.x;
    int b   = tid & 31;

    // stage W_hh rows for our 16 gate columns
    for (int i = tid; i < 16 * 256; i += 256) {
        int l = i >> 8, k = i & 255;
        int gc = (l >> 2) * 256 + j0 + (l & 3);
        w_s[i] = w_hh[gc * 256 + k];
    }

    // init c (register-resident, per activation thread) and h phase 0
    float c_reg = 0.f;
    if (tid < 128) {
        int jl = tid >> 5;
        int col = j0 + jl;
        c_reg = c0[dir * (BB*HH) + b * HH + col];
        g_h[0][dir][col][b] = h0[dir * (BB*HH) + b * HH + col];
    }
    __threadfence();
    dir_barrier(dir);

    int cg = tid >> 5;
    int l0 = cg * 2, l1 = l0 + 1;
    int gc0 = (l0 >> 2) * 256 + j0 + (l0 & 3);
    int gc1 = (l1 >> 2) * 256 + j0 + (l1 & 3);

    for (int t = 0; t < TT; ++t) {
        int tt = dir ? (TT - 1 - t) : t;
        int ph = t & 1;

        // stage full h into smem (coalesced flat copy from L2)
        const float* hg = &g_h[ph][dir][0][0];
        for (int i = tid; i < HH * BB; i += 256) h_s[i] = hg[i];
        __syncthreads();

        float a0 = g_ig[dir][tt][gc0][b];
        float a1 = g_ig[dir][tt][gc1][b];
        #pragma unroll 8
        for (int k = 0; k < 256; k += 4) {
            float4 w0 = *(const float4*)&w_s[l0 * 256 + k];
            float4 w1 = *(const float4*)&w_s[l1 * 256 + k];
            float hv0 = h_s[(k+0)*32 + b];
            float hv1 = h_s[(k+1)*32 + b];
            float hv2 = h_s[(k+2)*32 + b];
            float hv3 = h_s[(k+3)*32 + b];
            a0 += w0.x*hv0; a1 += w1.x*hv0;
            a0 += w0.y*hv1; a1 += w1.y*hv1;
            a0 += w0.z*hv2; a1 += w1.z*hv2;
            a0 += w0.w*hv3; a1 += w1.w*hv3;
        }
        g_s[l0 * 32 + b] = a0;
        g_s[l1 * 32 + b] = a1;
        __syncthreads();

        if (tid < 128) {
            int jl = tid >> 5;
            float gi = g_s[(0  + jl) * 32 + b];
            float gf = g_s[(4  + jl) * 32 + b];
            float gg = g_s[(8  + jl) * 32 + b];
            float go = g_s[(12 + jl) * 32 + b];
            float iv = 1.f / (1.f + expf(-gi));
            float fv = 1.f / (1.f + expf(-gf));
            float gv = tanhf(gg);
            float ov = 1.f / (1.f + expf(-go));
            c_reg = fv * c_reg + iv * gv;
            float hv = ov * tanhf(c_reg);
            int col = j0 + jl;
            g_h[ph ^ 1][dir][col][b] = hv;
            g_hall[tt][dir * HH + col][b] = hv;
        }
        __threadfence();
        dir_barrier(dir);
    }
}

// ---------------------------------------------------------------------------
// Kernel 3: feats[t][b][k] = hs[t][b][:] @ w_out[k][:] + b_out[k]
// grid = 512 (t), block = 768 (b = tid&31, k = tid>>5)
// ---------------------------------------------------------------------------
__global__ void __launch_bounds__(768) feats_kernel(
    const float* __restrict__ w_out, const float* __restrict__ b_out)
{
    extern __shared__ float sm[];
    float* h_sh = sm;                 // [hid][b]
    float* w_sh = sm + HID_ * BB;     // [k][hid]
    int t = blockIdx.x, tid = threadIdx.x;
    const float* hg = &g_hall[t][0][0];
    for (int i = tid; i < HID_ * BB; i += 768) h_sh[i] = hg[i];
    for (int i = tid; i < KK * HID_; i += 768) w_sh[i] = w_out[i];
    __syncthreads();
    int b = tid & 31, k = tid >> 5;
    float acc = 0.f;
    #pragma unroll 8
    for (int j = 0; j < HID_; ++j)
        acc += h_sh[j * 32 + b] * w_sh[k * HID_ + j];
    g_feats[t][b][k] = acc + __ldg(&b_out[k]);
}

// ---------------------------------------------------------------------------
// Kernel 4: Viterbi forward + backtrace. 1 warp per batch; bp in smem.
// Matches jnp.argmax first-max tie-breaking.
// ---------------------------------------------------------------------------
__global__ void __launch_bounds__(32) viterbi_kernel(
    const float* __restrict__ transitions, float* __restrict__ out)
{
    __shared__ unsigned char bp_s[TT][KK];
    int bb = blockIdx.x, lane = threadIdx.x;

    float tr[KK];
    #pragma unroll
    for (int j = 0; j < KK; ++j)
        tr[j] = (lane < KK) ? transitions[lane * KK + j] : 0.f;

    float fvv = (lane == START_TAG) ? 0.f : NEGV;

    for (int t = 0; t < TT; ++t) {
        float best = -3.402823466e38f; int arg = 0;
        #pragma unroll
        for (int p = 0; p < KK; ++p) {
            float s = __shfl_sync(0xffffffffu, fvv, p) + tr[p];
            if (s > best) { best = s; arg = p; }   // strict > keeps first max
        }
        float feat = (lane < KK) ? g_feats[t][bb][lane] : 0.f;
        fvv = best + feat;
        if (lane < KK) bp_s[t][lane] = (unsigned char)arg;
    }

    float term = (lane < KK) ? (fvv + transitions[STOP_TAG * KK + lane])
                             : -3.402823466e38f;
    int idx = lane;
    #pragma unroll
    for (int off = 16; off > 0; off >>= 1) {
        float v2 = __shfl_down_sync(0xffffffffu, term, off);
        int   i2 = __shfl_down_sync(0xffffffffu, idx,  off);
        if (v2 > term || (v2 == term && i2 < idx)) { term = v2; idx = i2; }
    }
    if (lane == 0) {
        out[bb] = term;                       // path score
        int tag = idx;
        for (int t = TT - 1; t >= 0; --t) {
            out[BB + bb * TT + t] = (float)tag;
            tag = bp_s[t][tag];
        }
    }
}

// ---------------------------------------------------------------------------
// Launch
// ---------------------------------------------------------------------------
static const int IG_SMEM  = (256 * 34 + 64 * 256) * 4;                 // 100352
static const int REC_SMEM = (16 * 256 + 256 * 32 + 16 * 32) * 4;      // 51200
static const int FE_SMEM  = (HID_ * BB + KK * HID_) * 4;              // 114688

extern "C" void kernel_launch(void* const* d_in, const int* in_sizes, int n_in,
                              void* d_out, int out_size)
{
    const int*   sentence    = (const int*)  d_in[0];
    const float* embedding   = (const float*)d_in[1];
    const float* w_ih_f      = (const float*)d_in[2];
    const float* w_hh_f      = (const float*)d_in[3];
    const float* b_ih_f      = (const float*)d_in[4];
    const float* b_hh_f      = (const float*)d_in[5];
    const float* w_ih_b      = (const float*)d_in[6];
    const float* w_hh_b      = (const float*)d_in[7];
    const float* b_ih_b      = (const float*)d_in[8];
    const float* b_hh_b      = (const float*)d_in[9];
    const float* w_out       = (const float*)d_in[10];
    const float* b_out       = (const float*)d_in[11];
    const float* transitions = (const float*)d_in[12];
    const float* h0          = (const float*)d_in[13];
    const float* c0          = (const float*)d_in[14];
    float* out = (float*)d_out;

    cudaFuncSetAttribute(ig_kernel,   cudaFuncAttributeMaxDynamicSharedMemorySize, IG_SMEM);
    cudaFuncSetAttribute(lstm_rec,    cudaFuncAttributeMaxDynamicSharedMemorySize, REC_SMEM);
    cudaFuncSetAttribute(feats_kernel,cudaFuncAttributeMaxDynamicSharedMemorySize, FE_SMEM);

    ig_kernel<<<1024, 256, IG_SMEM>>>(sentence, embedding,
                                      w_ih_f, b_ih_f, b_hh_f,
                                      w_ih_b, b_ih_b, b_hh_b);
    lstm_rec<<<128, 256, REC_SMEM>>>(w_hh_f, w_hh_b, h0, c0);
    feats_kernel<<<512, 768, FE_SMEM>>>(w_out, b_out);
    viterbi_kernel<<<32, 32>>>(transitions, out);
}

// round 5
// speedup vs baseline: 1.1097x; 1.1097x over previous
#include <cuda_runtime.h>
#include <math.h>
#include <stdint.h>

#define TT 512
#define BB 32
#define HH 256
#define EMB_ 256
#define KK 24
#define START_TAG 22
#define STOP_TAG 23
#define NEGV (-10000.0f)
typedef unsigned long long ull;

// ---------------------------------------------------------------------------
// Device scratch (__device__ globals: allocation-free rule)
// ---------------------------------------------------------------------------
__device__ float g_ig[2][TT][1024][BB];      // gate preactivations [dir][t][gatecol][b]
__device__ float g_hall[TT][512][BB];        // concat hidden [t][hid][b]
__device__ float g_h[2][2][4][HH][8];        // [phase][dir][bgrp][col][b_local]
__device__ float g_feats[TT][BB][KK];
__device__ unsigned g_cnt[8 * 32];           // counter per (dir,bgrp), 128B apart

// ---------------------------------------------------------------------------
// Packed fp32 + sync helpers
// ---------------------------------------------------------------------------
__device__ __forceinline__ ull ffma2(ull a, ull b, ull c) {
    ull d; asm("fma.rn.f32x2 %0, %1, %2, %3;" : "=l"(d) : "l"(a), "l"(b), "l"(c));
    return d;
}
__device__ __forceinline__ void unpack2(ull v, float& lo, float& hi) {
    asm("mov.b64 {%0, %1}, %2;" : "=f"(lo), "=f"(hi) : "l"(v));
}
__device__ __forceinline__ unsigned ld_acq(const unsigned* p) {
    unsigned v;
    asm volatile("ld.acquire.gpu.global.u32 %0, [%1];" : "=r"(v) : "l"(p) : "memory");
    return v;
}
__device__ __forceinline__ void red_rel(unsigned* p) {
    asm volatile("red.release.gpu.global.add.u32 [%0], %1;" :: "l"(p), "r"(1u) : "memory");
}

// ---------------------------------------------------------------------------
// Kernel 1: ig = emb[sent] @ W_ih^T + b_ih + b_hh
// Batch-packed FFMA2; per-batch chain over e ascending == R1 bit-exact.
// grid 1024 (d*512+t), block 256.
// smem: x_s[256][34] (R1 layout), wd[64][512] (64-col W chunk, duplicated)
// ---------------------------------------------------------------------------
__global__ void __launch_bounds__(256) ig_kernel(
    const int* __restrict__ sentence, const float* __restrict__ emb,
    const float* __restrict__ w_ih_f, const float* __restrict__ b_ih_f, const float* __restrict__ b_hh_f,
    const float* __restrict__ w_ih_b, const float* __restrict__ b_ih_b, const float* __restrict__ b_hh_b)
{
    extern __shared__ float sm[];
    float* x_s = sm;                  // 256*34
    float* wd  = sm + 256 * 34;       // 64*512 (duplicated)

    int d = blockIdx.x >> 9;
    int t = blockIdx.x & 511;
    int tid = threadIdx.x;

    // zero rec barrier counters (stream-ordered before lstm_rec)
    if (blockIdx.x == 0 && tid < 8) g_cnt[tid * 32] = 0u;

    const float* W  = d ? w_ih_b : w_ih_f;
    const float* bi = d ? b_ih_b : b_ih_f;
    const float* bh = d ? b_hh_b : b_hh_f;

    // gather embedding rows: x_s[e][b], e = tid (identical to R1)
    for (int b = 0; b < BB; ++b) {
        int tok = __ldg(&sentence[b * TT + t]);
        x_s[tid * 34 + b] = __ldg(&emb[(long)tok * EMB_ + tid]);
    }

    int bh2 = tid & 15;
    int b2  = 2 * bh2;
    int cg  = tid >> 4;

    for (int chunk = 0; chunk < 16; ++chunk) {
        int colBase = chunk * 64;
        __syncthreads();                       // prior reads done / gather done
        for (int i = tid; i < 64 * 256; i += 256) {
            float w = W[colBase * 256 + i];    // coalesced
            int r = i >> 8, k = i & 255;
            *(float2*)&wd[r * 512 + 2 * k] = make_float2(w, w);
        }
        __syncthreads();

        ull acc[4] = {0ull, 0ull, 0ull, 0ull};
        #pragma unroll 4
        for (int e2 = 0; e2 < 128; ++e2) {     // 2 e per iter, e ascending
            ull xa = *(const ull*)&x_s[(2 * e2)     * 34 + b2];
            ull xb = *(const ull*)&x_s[(2 * e2 + 1) * 34 + b2];
            #pragma unroll
            for (int j = 0; j < 4; ++j) {
                ulonglong2 wv = *(const ulonglong2*)&wd[(cg * 4 + j) * 512 + 4 * e2];
                acc[j] = ffma2(wv.x, xa, acc[j]);
                acc[j] = ffma2(wv.y, xb, acc[j]);
            }
        }
        #pragma unroll
        for (int j = 0; j < 4; ++j) {
            int col = colBase + cg * 4 + j;
            float bias = __ldg(&bi[col]) + __ldg(&bh[col]);
            float lo, hi; unpack2(acc[j], lo, hi);
            g_ig[d][t][col][b2]     = lo + bias;
            g_ig[d][t][col][b2 + 1] = hi + bias;
        }
    }
}

// ---------------------------------------------------------------------------
// Kernel 2: persistent BiLSTM recurrence, 2-D decomposition + FFMA2 (batch-
// packed; per-batch chain acc=ig then k ascending == R1 bit-exact).
// grid 128: dir = bx>>6, bgrp = (bx>>4)&3, cs = bx&15.  block 256.
// CTA owns h-cols [cs*16,+16) x batches [bgrp*8,+8); barrier = 16 CTAs (gid).
// smem: wd[64][516] (dup W slice), h2[128][20] (k-pair x b-pair), gbuf[64][8]
// ---------------------------------------------------------------------------
__global__ void __launch_bounds__(256) lstm_rec(
    const float* __restrict__ w_hh_f, const float* __restrict__ w_hh_b,
    const float* __restrict__ h0, const float* __restrict__ c0)
{
    extern __shared__ float sm[];
    float* wd   = sm;                          // 64 * 516
    float* h2   = sm + 64 * 516;               // 128 * 20
    float* gbuf = sm + 64 * 516 + 128 * 20;    // 64 * 8

    int bx   = blockIdx.x;
    int dir  = bx >> 6;
    int bgrp = (bx >> 4) & 3;
    int gid  = bx >> 4;
    int cs   = bx & 15;
    int j0   = cs * 16;
    int b0   = bgrp * 8;
    int tid  = threadIdx.x;
    const float* w_hh = dir ? w_hh_b : w_hh_f;

    // stage duplicated W_hh slice: l = gate*16 + jl
    for (int i = tid; i < 64 * 256; i += 256) {
        int l = i >> 8, k = i & 255;
        int gc = (l >> 4) * 256 + j0 + (l & 15);
        float w = w_hh[gc * 256 + k];
        *(float2*)&wd[l * 516 + 2 * k] = make_float2(w, w);
    }

    int bp = tid & 3;                          // batch pair 0..3
    int l  = tid >> 2;                         // gate row 0..63
    int gc_l = (l >> 4) * 256 + j0 + (l & 15);

    float c_reg = 0.f;
    if (tid < 128) {
        int jl = tid >> 3, b = tid & 7;
        c_reg = c0[dir * (BB * HH) + (b0 + b) * HH + (j0 + jl)];
    }

    for (int t = 0; t < TT; ++t) {
        int tt = dir ? (TT - 1 - t) : t;
        // prefetch gate preactivation pair before barrier wait
        ull ig01 = *(const ull*)&g_ig[dir][tt][gc_l][b0 + 2 * bp];

        if (t == 0) {
            for (int i = tid; i < 2048; i += 256) {
                int col = i >> 3, b = i & 7;
                h2[(col >> 1) * 20 + (b >> 1) * 4 + (col & 1) * 2 + (b & 1)] =
                    h0[dir * (BB * HH) + (b0 + b) * HH + col];
            }
        } else {
            if (tid == 0) {
                unsigned tgt = 16u * (unsigned)t;
                while (ld_acq(&g_cnt[gid * 32]) < tgt) { }
            }
            __syncthreads();
            const float* hg = &g_h[t & 1][dir][bgrp][0][0];   // [col][8b]
            for (int i = tid; i < 2048; i += 256) {
                int col = i >> 3, b = i & 7;
                h2[(col >> 1) * 20 + (b >> 1) * 4 + (col & 1) * 2 + (b & 1)] = hg[i];
            }
        }
        __syncthreads();

        ull acc = ig01;                        // chain starts at ig (== R1)
        #pragma unroll 8
        for (int kk = 0; kk < 128; ++kk) {     // k = 2kk, 2kk+1 ascending
            ulonglong2 hv = *(const ulonglong2*)&h2[kk * 20 + 4 * bp];
            ulonglong2 wv = *(const ulonglong2*)&wd[l * 516 + 4 * kk];
            acc = ffma2(wv.x, hv.x, acc);
            acc = ffma2(wv.y, hv.y, acc);
        }
        {
            float lo, hi; unpack2(acc, lo, hi);
            gbuf[l * 8 + 2 * bp]     = lo;
            gbuf[l * 8 + 2 * bp + 1] = hi;
        }
        __syncthreads();

        if (tid < 128) {
            int jl = tid >> 3, b = tid & 7;
            float gi = gbuf[(jl     ) * 8 + b];
            float gf = gbuf[(16 + jl) * 8 + b];
            float gg = gbuf[(32 + jl) * 8 + b];
            float go = gbuf[(48 + jl) * 8 + b];
            float iv = 1.f / (1.f + expf(-gi));
            float fv = 1.f / (1.f + expf(-gf));
            float gv = tanhf(gg);
            float ov = 1.f / (1.f + expf(-go));
            c_reg = fv * c_reg + iv * gv;
            float hv_ = ov * tanhf(c_reg);
            g_h[(t + 1) & 1][dir][bgrp][j0 + jl][b] = hv_;
            g_hall[tt][dir * HH + j0 + jl][b0 + b] = hv_;
        }
        __syncthreads();
        if (tid == 0) red_rel(&g_cnt[gid * 32]);
    }
}

// ---------------------------------------------------------------------------
// Kernel 3: feats (unchanged from R1 — bit-exact)
// ---------------------------------------------------------------------------
__global__ void __launch_bounds__(768) feats_kernel(
    const float* __restrict__ w_out, const float* __restrict__ b_out)
{
    extern __shared__ float sm[];
    float* h_sh = sm;                 // [hid][b]
    float* w_sh = sm + 512 * BB;      // [k][hid]
    int t = blockIdx.x, tid = threadIdx.x;
    const float* hg = &g_hall[t][0][0];
    for (int i = tid; i < 512 * BB; i += 768) h_sh[i] = hg[i];
    for (int i = tid; i < KK * 512; i += 768) w_sh[i] = w_out[i];
    __syncthreads();
    int b = tid & 31, k = tid >> 5;
    float acc = 0.f;
    #pragma unroll 8
    for (int j = 0; j < 512; ++j)
        acc += h_sh[j * 32 + b] * w_sh[k * 512 + j];
    g_feats[t][b][k] = acc + __ldg(&b_out[k]);
}

// ---------------------------------------------------------------------------
// Kernel 4: Viterbi — tree argmax (leftmost-max == first-max), feat prefetch.
// Value-identical to R1's scan.
// ---------------------------------------------------------------------------
__global__ void __launch_bounds__(32) viterbi_kernel(
    const float* __restrict__ transitions, float* __restrict__ out)
{
    __shared__ unsigned char bp_s[TT][KK];
    int bb = blockIdx.x, lane = threadIdx.x;

    float tr[KK];
    #pragma unroll
    for (int p = 0; p < KK; ++p)
        tr[p] = (lane < KK) ? __ldg(&transitions[lane * KK + p]) : NEGV;

    float fvv = (lane == START_TAG) ? 0.f : NEGV;
    float f0 = (lane < KK) ? __ldg(&g_feats[0][bb][lane]) : 0.f;
    float f1 = (lane < KK) ? __ldg(&g_feats[1][bb][lane]) : 0.f;

    for (int t = 0; t < TT; ++t) {
        float f2 = (t + 2 < TT && lane < KK) ? __ldg(&g_feats[t + 2][bb][lane]) : 0.f;

        float v[KK];
        #pragma unroll
        for (int p = 0; p < KK; ++p)
            v[p] = __shfl_sync(0xffffffffu, fvv, p) + tr[p];

        float bv[12]; int bi_[12];
        #pragma unroll
        for (int p = 0; p < 12; ++p) {
            bool ge = v[2*p] >= v[2*p+1];
            bv[p]  = ge ? v[2*p] : v[2*p+1];
            bi_[p] = ge ? 2*p : 2*p+1;
        }
        float cv[6]; int ci[6];
        #pragma unroll
        for (int p = 0; p < 6; ++p) {
            bool ge = bv[2*p] >= bv[2*p+1];
            cv[p] = ge ? bv[2*p] : bv[2*p+1];
            ci[p] = ge ? bi_[2*p] : bi_[2*p+1];
        }
        float dv[3]; int di[3];
        #pragma unroll
        for (int p = 0; p < 3; ++p) {
            bool ge = cv[2*p] >= cv[2*p+1];
            dv[p] = ge ? cv[2*p] : cv[2*p+1];
            di[p] = ge ? ci[2*p] : ci[2*p+1];
        }
        bool g01 = dv[0] >= dv[1];
        float ev = g01 ? dv[0] : dv[1];
        int   ei = g01 ? di[0] : di[1];
        bool gF = ev >= dv[2];
        float best = gF ? ev : dv[2];
        int   arg  = gF ? ei : di[2];

        fvv = best + f0;
        if (lane < KK) bp_s[t][lane] = (unsigned char)arg;
        f0 = f1; f1 = f2;
    }

    float term = (lane < KK) ? (fvv + __ldg(&transitions[STOP_TAG * KK + lane]))
                             : -3.402823466e38f;
    int idx = lane;
    #pragma unroll
    for (int off = 16; off > 0; off >>= 1) {
        float v2 = __shfl_down_sync(0xffffffffu, term, off);
        int   i2 = __shfl_down_sync(0xffffffffu, idx,  off);
        if (v2 > term || (v2 == term && i2 < idx)) { term = v2; idx = i2; }
    }
    if (lane == 0) {
        out[bb] = term;
        int tag = idx;
        for (int t = TT - 1; t >= 0; --t) {
            out[BB + bb * TT + t] = (float)tag;
            tag = bp_s[t][tag];
        }
    }
}

// ---------------------------------------------------------------------------
// Launch
// ---------------------------------------------------------------------------
static const int IG_SMEM  = (256 * 34 + 64 * 512) * 4;              // 165888
static const int REC_SMEM = (64 * 516 + 128 * 20 + 64 * 8) * 4;     // 144384
static const int FE_SMEM  = (512 * BB + KK * 512) * 4;              // 114688

extern "C" void kernel_launch(void* const* d_in, const int* in_sizes, int n_in,
                              void* d_out, int out_size)
{
    const int*   sentence    = (const int*)  d_in[0];
    const float* embedding   = (const float*)d_in[1];
    const float* w_ih_f      = (const float*)d_in[2];
    const float* w_hh_f      = (const float*)d_in[3];
    const float* b_ih_f      = (const float*)d_in[4];
    const float* b_hh_f      = (const float*)d_in[5];
    const float* w_ih_b      = (const float*)d_in[6];
    const float* w_hh_b      = (const float*)d_in[7];
    const float* b_ih_b      = (const float*)d_in[8];
    const float* b_hh_b      = (const float*)d_in[9];
    const float* w_out       = (const float*)d_in[10];
    const float* b_out       = (const float*)d_in[11];
    const float* transitions = (const float*)d_in[12];
    const float* h0          = (const float*)d_in[13];
    const float* c0          = (const float*)d_in[14];
    float* out = (float*)d_out;

    cudaFuncSetAttribute(ig_kernel,    cudaFuncAttributeMaxDynamicSharedMemorySize, IG_SMEM);
    cudaFuncSetAttribute(lstm_rec,     cudaFuncAttributeMaxDynamicSharedMemorySize, REC_SMEM);
    cudaFuncSetAttribute(feats_kernel, cudaFuncAttributeMaxDynamicSharedMemorySize, FE_SMEM);

    ig_kernel<<<1024, 256, IG_SMEM>>>(sentence, embedding,
                                      w_ih_f, b_ih_f, b_hh_f,
                                      w_ih_b, b_ih_b, b_hh_b);
    lstm_rec<<<128, 256, REC_SMEM>>>(w_hh_f, w_hh_b, h0, c0);
    feats_kernel<<<512, 768, FE_SMEM>>>(w_out, b_out);
    viterbi_kernel<<<32, 32>>>(transitions, out);
}

// round 6
// speedup vs baseline: 1.1147x; 1.0045x over previous
#include <cuda_runtime.h>
#include <math.h>
#include <stdint.h>

#define TT 512
#define BB 32
#define HH 256
#define EMB_ 256
#define KK 24
#define START_TAG 22
#define STOP_TAG 23
#define NEGV (-10000.0f)
typedef unsigned long long ull;

// ---------------------------------------------------------------------------
// Device scratch (__device__ globals: allocation-free rule)
// ---------------------------------------------------------------------------
__device__ float g_ig[2][TT][1024][BB];      // gate preactivations [dir][t][gatecol][b]
__device__ float g_hall[TT][512][BB];        // concat hidden [t][hid][b]
__device__ float g_h[2][2][4][HH][8];        // [phase][dir][bgrp][col][b_local]
__device__ float g_feats[TT][BB][KK];
__device__ unsigned g_cnt[8 * 32];           // counter per (dir,bgrp), 128B apart

// ---------------------------------------------------------------------------
// Packed fp32 + sync helpers
// ---------------------------------------------------------------------------
__device__ __forceinline__ ull ffma2(ull a, ull b, ull c) {
    ull d; asm("fma.rn.f32x2 %0, %1, %2, %3;" : "=l"(d) : "l"(a), "l"(b), "l"(c));
    return d;
}
__device__ __forceinline__ void unpack2(ull v, float& lo, float& hi) {
    asm("mov.b64 {%0, %1}, %2;" : "=f"(lo), "=f"(hi) : "l"(v));
}
__device__ __forceinline__ unsigned ld_acq(const unsigned* p) {
    unsigned v;
    asm volatile("ld.acquire.gpu.global.u32 %0, [%1];" : "=r"(v) : "l"(p) : "memory");
    return v;
}
__device__ __forceinline__ void red_rel(unsigned* p) {
    asm volatile("red.release.gpu.global.add.u32 [%0], %1;" :: "l"(p), "r"(1u) : "memory");
}

// ---------------------------------------------------------------------------
// Kernel 1: ig = emb[sent] @ W_ih^T + b_ih + b_hh
// Batch-packed FFMA2; per-batch chain over e ascending == R1 bit-exact.
// grid 1024 (d*512+t), block 256.
// smem: x_s[256][34] (R1 layout), wd[64][512] (64-col W chunk, duplicated)
// ---------------------------------------------------------------------------
__global__ void __launch_bounds__(256) ig_kernel(
    const int* __restrict__ sentence, const float* __restrict__ emb,
    const float* __restrict__ w_ih_f, const float* __restrict__ b_ih_f, const float* __restrict__ b_hh_f,
    const float* __restrict__ w_ih_b, const float* __restrict__ b_ih_b, const float* __restrict__ b_hh_b)
{
    extern __shared__ float sm[];
    float* x_s = sm;                  // 256*34
    float* wd  = sm + 256 * 34;       // 64*512 (duplicated)

    int d = blockIdx.x >> 9;
    int t = blockIdx.x & 511;
    int tid = threadIdx.x;

    // zero rec barrier counters (stream-ordered before lstm_rec)
    if (blockIdx.x == 0 && tid < 8) g_cnt[tid * 32] = 0u;

    const float* W  = d ? w_ih_b : w_ih_f;
    const float* bi = d ? b_ih_b : b_ih_f;
    const float* bh = d ? b_hh_b : b_hh_f;

    // gather embedding rows: x_s[e][b], e = tid (identical to R1)
    for (int b = 0; b < BB; ++b) {
        int tok = __ldg(&sentence[b * TT + t]);
        x_s[tid * 34 + b] = __ldg(&emb[(long)tok * EMB_ + tid]);
    }

    int bh2 = tid & 15;
    int b2  = 2 * bh2;
    int cg  = tid >> 4;

    for (int chunk = 0; chunk < 16; ++chunk) {
        int colBase = chunk * 64;
        __syncthreads();                       // prior reads done / gather done
        for (int i = tid; i < 64 * 256; i += 256) {
            float w = W[colBase * 256 + i];    // coalesced
            int r = i >> 8, k = i & 255;
            *(float2*)&wd[r * 512 + 2 * k] = make_float2(w, w);
        }
        __syncthreads();

        ull acc[4] = {0ull, 0ull, 0ull, 0ull};
        #pragma unroll 4
        for (int e2 = 0; e2 < 128; ++e2) {     // 2 e per iter, e ascending
            ull xa = *(const ull*)&x_s[(2 * e2)     * 34 + b2];
            ull xb = *(const ull*)&x_s[(2 * e2 + 1) * 34 + b2];
            #pragma unroll
            for (int j = 0; j < 4; ++j) {
                ulonglong2 wv = *(const ulonglong2*)&wd[(cg * 4 + j) * 512 + 4 * e2];
                acc[j] = ffma2(wv.x, xa, acc[j]);
                acc[j] = ffma2(wv.y, xb, acc[j]);
            }
        }
        #pragma unroll
        for (int j = 0; j < 4; ++j) {
            int col = colBase + cg * 4 + j;
            float bias = __ldg(&bi[col]) + __ldg(&bh[col]);
            float lo, hi; unpack2(acc[j], lo, hi);
            g_ig[d][t][col][b2]     = lo + bias;
            g_ig[d][t][col][b2 + 1] = hi + bias;
        }
    }
}

// ---------------------------------------------------------------------------
// Kernel 2: persistent BiLSTM recurrence, 2-D decomposition + FFMA2 (batch-
// packed; per-batch chain acc=ig then k ascending == R1 bit-exact).
// grid 128: dir = bx>>6, bgrp = (bx>>4)&3, cs = bx&15.  block 256.
// CTA owns h-cols [cs*16,+16) x batches [bgrp*8,+8); barrier = 16 CTAs (gid).
// smem: wd[64][516] (dup W slice), h2[128][20] (k-pair x b-pair), gbuf[64][8]
// ---------------------------------------------------------------------------
__global__ void __launch_bounds__(256) lstm_rec(
    const float* __restrict__ w_hh_f, const float* __restrict__ w_hh_b,
    const float* __restrict__ h0, const float* __restrict__ c0)
{
    extern __shared__ float sm[];
    float* wd   = sm;                          // 64 * 516
    float* h2   = sm + 64 * 516;               // 128 * 20
    float* gbuf = sm + 64 * 516 + 128 * 20;    // 64 * 8

    int bx   = blockIdx.x;
    int dir  = bx >> 6;
    int bgrp = (bx >> 4) & 3;
    int gid  = bx >> 4;
    int cs   = bx & 15;
    int j0   = cs * 16;
    int b0   = bgrp * 8;
    int tid  = threadIdx.x;
    const float* w_hh = dir ? w_hh_b : w_hh_f;

    // stage duplicated W_hh slice: l = gate*16 + jl
    for (int i = tid; i < 64 * 256; i += 256) {
        int l = i >> 8, k = i & 255;
        int gc = (l >> 4) * 256 + j0 + (l & 15);
        float w = w_hh[gc * 256 + k];
        *(float2*)&wd[l * 516 + 2 * k] = make_float2(w, w);
    }

    int bp = tid & 3;                          // batch pair 0..3
    int l  = tid >> 2;                         // gate row 0..63
    int gc_l = (l >> 4) * 256 + j0 + (l & 15);

    float c_reg = 0.f;
    if (tid < 128) {
        int jl = tid >> 3, b = tid & 7;
        c_reg = c0[dir * (BB * HH) + (b0 + b) * HH + (j0 + jl)];
    }

    for (int t = 0; t < TT; ++t) {
        int tt = dir ? (TT - 1 - t) : t;
        // prefetch gate preactivation pair before barrier wait
        ull ig01 = *(const ull*)&g_ig[dir][tt][gc_l][b0 + 2 * bp];

        if (t == 0) {
            for (int i = tid; i < 2048; i += 256) {
                int col = i >> 3, b = i & 7;
                h2[(col >> 1) * 20 + (b >> 1) * 4 + (col & 1) * 2 + (b & 1)] =
                    h0[dir * (BB * HH) + (b0 + b) * HH + col];
            }
        } else {
            if (tid == 0) {
                unsigned tgt = 16u * (unsigned)t;
                while (ld_acq(&g_cnt[gid * 32]) < tgt) { }
            }
            __syncthreads();
            const float* hg = &g_h[t & 1][dir][bgrp][0][0];   // [col][8b]
            for (int i = tid; i < 2048; i += 256) {
                int col = i >> 3, b = i & 7;
                h2[(col >> 1) * 20 + (b >> 1) * 4 + (col & 1) * 2 + (b & 1)] = hg[i];
            }
        }
        __syncthreads();

        ull acc = ig01;                        // chain starts at ig (== R1)
        #pragma unroll 8
        for (int kk = 0; kk < 128; ++kk) {     // k = 2kk, 2kk+1 ascending
            ulonglong2 hv = *(const ulonglong2*)&h2[kk * 20 + 4 * bp];
            ulonglong2 wv = *(const ulonglong2*)&wd[l * 516 + 4 * kk];
            acc = ffma2(wv.x, hv.x, acc);
            acc = ffma2(wv.y, hv.y, acc);
        }
        {
            float lo, hi; unpack2(acc, lo, hi);
            gbuf[l * 8 + 2 * bp]     = lo;
            gbuf[l * 8 + 2 * bp + 1] = hi;
        }
        __syncthreads();

        if (tid < 128) {
            int jl = tid >> 3, b = tid & 7;
            float gi = gbuf[(jl     ) * 8 + b];
            float gf = gbuf[(16 + jl) * 8 + b];
            float gg = gbuf[(32 + jl) * 8 + b];
            float go = gbuf[(48 + jl) * 8 + b];
            float iv = 1.f / (1.f + expf(-gi));
            float fv = 1.f / (1.f + expf(-gf));
            float gv = tanhf(gg);
            float ov = 1.f / (1.f + expf(-go));
            c_reg = fv * c_reg + iv * gv;
            float hv_ = ov * tanhf(c_reg);
            g_h[(t + 1) & 1][dir][bgrp][j0 + jl][b] = hv_;
            g_hall[tt][dir * HH + j0 + jl][b0 + b] = hv_;
        }
        __syncthreads();
        if (tid == 0) red_rel(&g_cnt[gid * 32]);
    }
}

// ---------------------------------------------------------------------------
// Kernel 3: feats (unchanged from R1 — bit-exact)
// ---------------------------------------------------------------------------
__global__ void __launch_bounds__(768) feats_kernel(
    const float* __restrict__ w_out, const float* __restrict__ b_out)
{
    extern __shared__ float sm[];
    float* h_sh = sm;                 // [hid][b]
    float* w_sh = sm + 512 * BB;      // [k][hid]
    int t = blockIdx.x, tid = threadIdx.x;
    const float* hg = &g_hall[t][0][0];
    for (int i = tid; i < 512 * BB; i += 768) h_sh[i] = hg[i];
    for (int i = tid; i < KK * 512; i += 768) w_sh[i] = w_out[i];
    __syncthreads();
    int b = tid & 31, k = tid >> 5;
    float acc = 0.f;
    #pragma unroll 8
    for (int j = 0; j < 512; ++j)
        acc += h_sh[j * 32 + b] * w_sh[k * 512 + j];
    g_feats[t][b][k] = acc + __ldg(&b_out[k]);
}

// ---------------------------------------------------------------------------
// Kernel 4: Viterbi — tree argmax (leftmost-max == first-max), feat prefetch.
// Value-identical to R1's scan.
// ---------------------------------------------------------------------------
__global__ void __launch_bounds__(32) viterbi_kernel(
    const float* __restrict__ transitions, float* __restrict__ out)
{
    __shared__ unsigned char bp_s[TT][KK];
    int bb = blockIdx.x, lane = threadIdx.x;

    float tr[KK];
    #pragma unroll
    for (int p = 0; p < KK; ++p)
        tr[p] = (lane < KK) ? __ldg(&transitions[lane * KK + p]) : NEGV;

    float fvv = (lane == START_TAG) ? 0.f : NEGV;
    float f0 = (lane < KK) ? __ldg(&g_feats[0][bb][lane]) : 0.f;
    float f1 = (lane < KK) ? __ldg(&g_feats[1][bb][lane]) : 0.f;

    for (int t = 0; t < TT; ++t) {
        float f2 = (t + 2 < TT && lane < KK) ? __ldg(&g_feats[t + 2][bb][lane]) : 0.f;

        float v[KK];
        #pragma unroll
        for (int p = 0; p < KK; ++p)
            v[p] = __shfl_sync(0xffffffffu, fvv, p) + tr[p];

        float bv[12]; int bi_[12];
        #pragma unroll
        for (int p = 0; p < 12; ++p) {
            bool ge = v[2*p] >= v[2*p+1];
            bv[p]  = ge ? v[2*p] : v[2*p+1];
            bi_[p] = ge ? 2*p : 2*p+1;
        }
        float cv[6]; int ci[6];
        #pragma unroll
        for (int p = 0; p < 6; ++p) {
            bool ge = bv[2*p] >= bv[2*p+1];
            cv[p] = ge ? bv[2*p] : bv[2*p+1];
            ci[p] = ge ? bi_[2*p] : bi_[2*p+1];
        }
        float dv[3]; int di[3];
        #pragma unroll
        for (int p = 0; p < 3; ++p) {
            bool ge = cv[2*p] >= cv[2*p+1];
            dv[p] = ge ? cv[2*p] : cv[2*p+1];
            di[p] = ge ? ci[2*p] : ci[2*p+1];
        }
        bool g01 = dv[0] >= dv[1];
        float ev = g01 ? dv[0] : dv[1];
        int   ei = g01 ? di[0] : di[1];
        bool gF = ev >= dv[2];
        float best = gF ? ev : dv[2];
        int   arg  = gF ? ei : di[2];

        fvv = best + f0;
        if (lane < KK) bp_s[t][lane] = (unsigned char)arg;
        f0 = f1; f1 = f2;
    }

    float term = (lane < KK) ? (fvv + __ldg(&transitions[STOP_TAG * KK + lane]))
                             : -3.402823466e38f;
    int idx = lane;
    #pragma unroll
    for (int off = 16; off > 0; off >>= 1) {
        float v2 = __shfl_down_sync(0xffffffffu, term, off);
        int   i2 = __shfl_down_sync(0xffffffffu, idx,  off);
        if (v2 > term || (v2 == term && i2 < idx)) { term = v2; idx = i2; }
    }
    if (lane == 0) {
        out[bb] = term;
        int tag = idx;
        for (int t = TT - 1; t >= 0; --t) {
            out[BB + bb * TT + t] = (float)tag;
            tag = bp_s[t][tag];
        }
    }
}

// ---------------------------------------------------------------------------
// Launch
// ---------------------------------------------------------------------------
static const int IG_SMEM  = (256 * 34 + 64 * 512) * 4;              // 165888
static const int REC_SMEM = (64 * 516 + 128 * 20 + 64 * 8) * 4;     // 144384
static const int FE_SMEM  = (512 * BB + KK * 512) * 4;              // 114688

extern "C" void kernel_launch(void* const* d_in, const int* in_sizes, int n_in,
                              void* d_out, int out_size)
{
    const int*   sentence    = (const int*)  d_in[0];
    const float* embedding   = (const float*)d_in[1];
    const float* w_ih_f      = (const float*)d_in[2];
    const float* w_hh_f      = (const float*)d_in[3];
    const float* b_ih_f      = (const float*)d_in[4];
    const float* b_hh_f      = (const float*)d_in[5];
    const float* w_ih_b      = (const float*)d_in[6];
    const float* w_hh_b      = (const float*)d_in[7];
    const float* b_ih_b      = (const float*)d_in[8];
    const float* b_hh_b      = (const float*)d_in[9];
    const float* w_out       = (const float*)d_in[10];
    const float* b_out       = (const float*)d_in[11];
    const float* transitions = (const float*)d_in[12];
    const float* h0          = (const float*)d_in[13];
    const float* c0          = (const float*)d_in[14];
    float* out = (float*)d_out;

    cudaFuncSetAttribute(ig_kernel,    cudaFuncAttributeMaxDynamicSharedMemorySize, IG_SMEM);
    cudaFuncSetAttribute(lstm_rec,     cudaFuncAttributeMaxDynamicSharedMemorySize, REC_SMEM);
    cudaFuncSetAttribute(feats_kernel, cudaFuncAttributeMaxDynamicSharedMemorySize, FE_SMEM);

    ig_kernel<<<1024, 256, IG_SMEM>>>(sentence, embedding,
                                      w_ih_f, b_ih_f, b_hh_f,
                                      w_ih_b, b_ih_b, b_hh_b);
    lstm_rec<<<128, 256, REC_SMEM>>>(w_hh_f, w_hh_b, h0, c0);
    feats_kernel<<<512, 768, FE_SMEM>>>(w_out, b_out);
    viterbi_kernel<<<32, 32>>>(transitions, out);
}